// round 6
// baseline (speedup 1.0000x reference)
#include <cuda_runtime.h>
#include <math.h>

// ----------------------------------------------------------------------------
// ModulatedDeformableConv2d (DCNv2-style) with residual offset output.
//   B=4, CIN=COUT=128, K=3, S=1, P=1, D=1, H=W=96, MASK_SCALE=2
// Outputs (concatenated in d_out, float32):
//   out    [4,128,96,96]  then  offset [4,18,96,96]
// ----------------------------------------------------------------------------

namespace {
constexpr int Bn    = 4;
constexpr int CIN_  = 128;
constexpr int COUT_ = 128;
constexpr int Hd    = 96;
constexpr int Wd    = 96;
constexpr int HW_   = Hd * Wd;               // 9216
constexpr int KKd   = CIN_ * 9;              // 1152
constexpr int OUT_ELEMS = Bn * COUT_ * HW_;  // 4718592
}

__device__ float g_om[Bn * 27 * HW_];        // offset/mask conv scratch

// ---- packed fp32x2 helpers (FFMA2: only reachable via PTX) -----------------
__device__ __forceinline__ void fma2(unsigned long long& d,
                                     unsigned long long a,
                                     unsigned long long b) {
    asm("fma.rn.f32x2 %0, %1, %2, %0;" : "+l"(d) : "l"(a), "l"(b));
}
__device__ __forceinline__ unsigned long long dup2(float v) {
    unsigned long long r;
    asm("mov.b64 %0, {%1, %1};" : "=l"(r) : "f"(v));
    return r;
}
__device__ __forceinline__ float2 unpk(unsigned long long v) {
    float2 r;
    asm("mov.b64 {%0, %1}, %2;" : "=f"(r.x), "=f"(r.y) : "l"(v));
    return r;
}

// ----------------------------------------------------------------------------
// Kernel 1: om = conv3x3(x, w_offmask), 27 ch, pad=1. Direct conv with
// channel-chunked row cache. Block = (b, h, half-row of 48 px), 128 threads.
// micro: 4 oc x 3 px. Writes g_om (27 ch) + offset output (18 ch).
// Grid: 4*96*2 = 768.
// ----------------------------------------------------------------------------
__global__ __launch_bounds__(128) void offconv_kernel(
    const float* __restrict__ x,
    const float* __restrict__ wom,
    float* __restrict__ outp)
{
    __shared__ __align__(16) float xr[4][3][52];  // 4 ch x 3 rows x 50(+pad) cols
    __shared__ __align__(16) float wA[4][9][32];  // [c][tap][oc] (27 used)

    const int bx = blockIdx.x;
    const int wt = bx & 1;
    const int h  = (bx >> 1) % Hd;
    const int b  = bx / (2 * Hd);
    const int w0 = wt * 48;
    const int t  = threadIdx.x;
    const int ty = t >> 4;            // 0..7  -> oc0 = ty*4
    const int tx = t & 15;            // 0..15 -> px0 = tx*3
    const int oc0 = ty * 4;
    const int px0 = tx * 3;

    // zero the pad weight columns (oc 27..31) once
    for (int e = t; e < 4 * 9 * 5; e += 128) {
        const int c  = e / 45;
        const int r  = e % 45;
        wA[c][r / 5][27 + r % 5] = 0.f;
    }

    float acc[4][3];
#pragma unroll
    for (int i = 0; i < 4; i++)
#pragma unroll
        for (int j = 0; j < 3; j++) acc[i][j] = 0.f;

    const float* xb = x + b * CIN_ * HW_;

    for (int c0 = 0; c0 < CIN_; c0 += 4) {
        __syncthreads();
        // ---- fill row cache: cols w0-1 .. w0+48 (idx 0..49), zero OOB
        for (int e = t; e < 4 * 3 * 52; e += 128) {
            const int c  = e / 156;
            const int rr = e % 156;
            const int r  = rr / 52;
            const int cx = rr % 52;
            const int y   = h + r - 1;
            const int col = w0 + cx - 1;
            float v = 0.f;
            if (cx < 50 && (unsigned)y < (unsigned)Hd && (unsigned)col < (unsigned)Wd)
                v = __ldg(xb + (c0 + c) * HW_ + y * Wd + col);
            xr[c][r][cx] = v;
        }
        // ---- fill transposed weights [c][tap][oc] (coalesced in (c,tap))
        for (int e = t; e < 27 * 36; e += 128) {
            const int oc = e / 36;
            const int ck = e % 36;
            wA[ck / 9][ck % 9][oc] = __ldg(wom + oc * KKd + (c0 + ck / 9) * 9 + (ck % 9));
        }
        __syncthreads();

#pragma unroll
        for (int c = 0; c < 4; c++) {
#pragma unroll
            for (int ki = 0; ki < 3; ki++) {
                float r[5];
#pragma unroll
                for (int q = 0; q < 5; q++) r[q] = xr[c][ki][px0 + q];
#pragma unroll
                for (int kj = 0; kj < 3; kj++) {
                    float4 a = *reinterpret_cast<const float4*>(&wA[c][ki * 3 + kj][oc0]);
                    float av[4] = {a.x, a.y, a.z, a.w};
#pragma unroll
                    for (int i = 0; i < 4; i++)
#pragma unroll
                        for (int j = 0; j < 3; j++)
                            acc[i][j] = fmaf(av[i], r[kj + j], acc[i][j]);
                }
            }
        }
    }

    // ---- epilogue: g_om (27 ch) + offset output (18 ch)
#pragma unroll
    for (int i = 0; i < 4; i++) {
        const int oc = oc0 + i;
        if (oc < 27) {
#pragma unroll
            for (int j = 0; j < 3; j++) {
                const int w = w0 + px0 + j;
                const float v = acc[i][j];
                g_om[(b * 27 + oc) * HW_ + h * Wd + w] = v;
                if (oc < 18)
                    outp[OUT_ELEMS + (b * 18 + oc) * HW_ + h * Wd + w] = v;
            }
        }
    }
}

// ----------------------------------------------------------------------------
// Kernel 2: fused deformable im2col + GEMM with packed f32x2 FMAs.
// Block tile: 128 oc x 48 px (one b, one row h, half-row), 128 threads.
// micro-tile: 8 oc (4 packed pairs) x 6 px. Accumulators are f32x2 oc-pairs:
// A pairs come straight out of LDS.128, only B scalars need lane duplication.
// Grid: 4*96*2 = 768.
// ----------------------------------------------------------------------------
__global__ __launch_bounds__(128) void dcn_main_kernel(
    const float* __restrict__ x,
    const float* __restrict__ weight,
    const float* __restrict__ bias,
    float* __restrict__ outp)
{
    __shared__ __align__(16) float As[32][132];   // [kk][oc]
    __shared__ __align__(16) float Bs[32][52];    // [kk][px]
    __shared__ int4   sIdx[9 * 48];               // [tap][px] corner indices
    __shared__ float4 sWgt[9 * 48];               // [tap][px] corner weights
    __shared__ float  sBias[128];

    const int bx = blockIdx.x;
    const int wt = bx & 1;
    const int h  = (bx >> 1) % Hd;
    const int b  = bx / (2 * Hd);
    const int w0 = wt * 48;
    const int t  = threadIdx.x;
    const int ty = t >> 3;            // 0..15 -> oc0 = ty*8
    const int tx = t & 7;             // 0..7  -> px0 = tx*6
    const int oc0 = ty * 8;
    const int px0 = tx * 6;

    sBias[t] = bias[t];

    // ---- precompute bilinear sampling metadata per (tap, pixel)
    for (int e = t; e < 9 * 48; e += 128) {
        const int k = e / 48;
        const int p = e % 48;
        const int w = w0 + p;
        const float* om = g_om + (b * 27) * HW_ + h * Wd + w;
        const float o1 = om[k * HW_];
        const float o2 = om[(9 + k) * HW_];
        const float mr = om[(18 + k) * HW_];
        const float m  = 2.f / (1.f + expf(-mr));

        const int ki = k / 3, kj = k - ki * 3;
        const float py  = (float)(h - 1 + ki) + o1;
        const float pxf = (float)(w - 1 + kj) + o2;
        const float y0f = floorf(py), x0f = floorf(pxf);
        const float ly = py - y0f, lx = pxf - x0f;
        const int y0 = (int)y0f, x0 = (int)x0f;
        const int y1 = y0 + 1,  x1 = x0 + 1;

        const float v00 = ((unsigned)y0 < (unsigned)Hd && (unsigned)x0 < (unsigned)Wd) ? 1.f : 0.f;
        const float v01 = ((unsigned)y0 < (unsigned)Hd && (unsigned)x1 < (unsigned)Wd) ? 1.f : 0.f;
        const float v10 = ((unsigned)y1 < (unsigned)Hd && (unsigned)x0 < (unsigned)Wd) ? 1.f : 0.f;
        const float v11 = ((unsigned)y1 < (unsigned)Hd && (unsigned)x1 < (unsigned)Wd) ? 1.f : 0.f;

        const int y0c = min(max(y0, 0), Hd - 1), y1c = min(max(y1, 0), Hd - 1);
        const int x0c = min(max(x0, 0), Wd - 1), x1c = min(max(x1, 0), Wd - 1);

        sIdx[e] = make_int4(y0c * Wd + x0c, y0c * Wd + x1c,
                            y1c * Wd + x0c, y1c * Wd + x1c);
        const float hy = 1.f - ly, hx = 1.f - lx;
        sWgt[e] = make_float4(hy * hx * m * v00, hy * lx * m * v01,
                              ly * hx * m * v10, ly * lx * m * v11);
    }
    __syncthreads();

    unsigned long long acc[4][6];
#pragma unroll
    for (int i = 0; i < 4; i++)
#pragma unroll
        for (int j = 0; j < 6; j++) acc[i][j] = 0ull;

    const float* xb = x + b * CIN_ * HW_;

    for (int kc = 0; kc < KKd; kc += 32) {
        // ---- As fill: 8 float4 per thread, coalesced (128B runs per oc)
#pragma unroll
        for (int i = 0; i < 8; i++) {
            const int f   = t + i * 128;
            const int oc  = f >> 3;
            const int kkq = (f & 7) << 2;
            float4 wv = *reinterpret_cast<const float4*>(weight + oc * KKd + kc + kkq);
            As[kkq + 0][oc] = wv.x;
            As[kkq + 1][oc] = wv.y;
            As[kkq + 2][oc] = wv.z;
            As[kkq + 3][oc] = wv.w;
        }
        // ---- Bs fill: deformable-sampled columns (4 gathers per element)
#pragma unroll
        for (int i = 0; i < 12; i++) {
            const int e    = t + i * 128;
            const int kk   = e / 48;
            const int p    = e % 48;
            const int kidx = kc + kk;
            const int c    = kidx / 9;
            const int k    = kidx - c * 9;
            const int4   id = sIdx[k * 48 + p];
            const float4 wv = sWgt[k * 48 + p];
            const float* xc = xb + c * HW_;
            Bs[kk][p] = wv.x * __ldg(xc + id.x)
                      + wv.y * __ldg(xc + id.y)
                      + wv.z * __ldg(xc + id.z)
                      + wv.w * __ldg(xc + id.w);
        }
        __syncthreads();

#pragma unroll
        for (int kk = 0; kk < 32; kk++) {
            ulonglong2 aA = *reinterpret_cast<const ulonglong2*>(&As[kk][oc0]);
            ulonglong2 aB = *reinterpret_cast<const ulonglong2*>(&As[kk][oc0 + 4]);
            unsigned long long a[4] = {aA.x, aA.y, aB.x, aB.y};
            float2 b0 = *reinterpret_cast<const float2*>(&Bs[kk][px0]);
            float2 b1 = *reinterpret_cast<const float2*>(&Bs[kk][px0 + 2]);
            float2 b2 = *reinterpret_cast<const float2*>(&Bs[kk][px0 + 4]);
            unsigned long long d[6] = {dup2(b0.x), dup2(b0.y), dup2(b1.x),
                                       dup2(b1.y), dup2(b2.x), dup2(b2.y)};
#pragma unroll
            for (int i = 0; i < 4; i++)
#pragma unroll
                for (int j = 0; j < 6; j++)
                    fma2(acc[i][j], a[i], d[j]);
        }
        __syncthreads();
    }

    // ---- epilogue: unpack oc-pairs, add bias, store
    const int w = w0 + px0;
#pragma unroll
    for (int i = 0; i < 4; i++) {
        const int oce = oc0 + 2 * i;
        const float be = sBias[oce];
        const float bo = sBias[oce + 1];
        float* pe = outp + (b * COUT_ + oce) * HW_ + h * Wd + w;
        float* po = pe + HW_;
#pragma unroll
        for (int j = 0; j < 6; j++) {
            float2 v = unpk(acc[i][j]);
            pe[j] = v.x + be;
            po[j] = v.y + bo;
        }
    }
}

// ----------------------------------------------------------------------------
extern "C" void kernel_launch(void* const* d_in, const int* in_sizes, int n_in,
                              void* d_out, int out_size)
{
    const float* x    = (const float*)d_in[0];   // [4,128,96,96]
    const float* wgt  = (const float*)d_in[1];   // [128,128,3,3]
    const float* bias = (const float*)d_in[2];   // [128]
    const float* wom  = (const float*)d_in[3];   // [27,128,3,3]
    float* outp = (float*)d_out;

    offconv_kernel<<<Bn * Hd * 2, 128>>>(x, wom, outp);          // 768 blocks
    dcn_main_kernel<<<Bn * Hd * 2, 128>>>(x, wgt, bias, outp);   // 768 blocks
}

// round 8
// speedup vs baseline: 1.1474x; 1.1474x over previous
#include <cuda_runtime.h>
#include <math.h>

// ----------------------------------------------------------------------------
// ModulatedDeformableConv2d (DCNv2-style) with residual offset output.
//   B=4, CIN=COUT=128, K=3, S=1, P=1, D=1, H=W=96, MASK_SCALE=2
// d_out: out [4,128,96,96] then offset [4,18,96,96], float32.
// ----------------------------------------------------------------------------

namespace {
constexpr int Bn    = 4;
constexpr int CIN_  = 128;
constexpr int COUT_ = 128;
constexpr int Hd    = 96;
constexpr int Wd    = 96;
constexpr int HW_   = 9216;
constexpr int KKd   = CIN_ * 9;              // 1152
constexpr int OUT_ELEMS = Bn * COUT_ * HW_;  // 4718592
constexpr int KC    = 16;                    // k-chunk
}

__device__ float g_om[Bn * 27 * HW_];             // offset/mask conv scratch
__device__ __align__(16) float g_wT [KKd * 128];  // weight transposed [kk][oc]
__device__ __align__(16) float g_wOmT[KKd * 32];  // w_offmask transposed [kk][oc<32]

// ---- packed fp32x2 + cp.async helpers --------------------------------------
__device__ __forceinline__ void fma2(unsigned long long& d,
                                     unsigned long long a,
                                     unsigned long long b) {
    asm("fma.rn.f32x2 %0, %1, %2, %0;" : "+l"(d) : "l"(a), "l"(b));
}
__device__ __forceinline__ float2 unpk(unsigned long long v) {
    float2 r;
    asm("mov.b64 {%0, %1}, %2;" : "=f"(r.x), "=f"(r.y) : "l"(v));
    return r;
}
__device__ __forceinline__ void cp16(void* dst_smem, const void* src) {
    unsigned d = (unsigned)__cvta_generic_to_shared(dst_smem);
    asm volatile("cp.async.ca.shared.global [%0], [%1], 16;" :: "r"(d), "l"(src));
}
__device__ __forceinline__ void cp_commit() {
    asm volatile("cp.async.commit_group;");
}
__device__ __forceinline__ void cp_wait0() {
    asm volatile("cp.async.wait_group 0;" ::: "memory");
}

// ----------------------------------------------------------------------------
// Kernel 0: one-time (per launch) weight transposes.
// ----------------------------------------------------------------------------
__global__ __launch_bounds__(256) void prep_kernel(
    const float* __restrict__ weight, const float* __restrict__ wom)
{
    const int idx = blockIdx.x * 256 + threadIdx.x;     // 0..184319
    if (idx < KKd * 128) {
        const int kk = idx >> 7, oc = idx & 127;
        g_wT[idx] = __ldg(weight + oc * KKd + kk);
    } else {
        const int j = idx - KKd * 128;
        const int kk = j >> 5, oc = j & 31;
        g_wOmT[j] = (oc < 27) ? __ldg(wom + oc * KKd + kk) : 0.f;
    }
}

// ----------------------------------------------------------------------------
// Kernel 1: om = conv3x3(x, w_offmask), 27 ch, pad=1.
// Block = (b, h, half-row of 48 px), 128 thr. micro: 4 oc (2 f32x2 pairs) x 3 px.
// Double-buffered c-chunks (4 ch), ONE sync per chunk. Row cache stored
// lane-duplicated so packed B operands come straight from LDS.
// ----------------------------------------------------------------------------
__global__ __launch_bounds__(128) void offconv_kernel(
    const float* __restrict__ x,
    float* __restrict__ outp)
{
    __shared__ __align__(16) float xr[2][4][3][104];  // dup-stored, cols 0..49
    __shared__ __align__(16) float wA[2][4][9][32];   // [c][tap][oc]

    const int bx = blockIdx.x;
    const int wt = bx & 1;
    const int h  = (bx >> 1) % Hd;
    const int b  = bx / (2 * Hd);
    const int w0 = wt * 48;
    const int t  = threadIdx.x;
    const int ty = t >> 4;            // 0..7  -> oc0 = ty*4
    const int tx = t & 15;            // 0..15 -> px0 = tx*3
    const int oc0 = ty * 4;
    const int px0 = tx * 3;

    unsigned long long acc[2][3];
#pragma unroll
    for (int i = 0; i < 2; i++)
#pragma unroll
        for (int j = 0; j < 3; j++) acc[i][j] = 0ull;

    const float* xb = x + b * CIN_ * HW_;
    int buf = 0;

    for (int c0 = 0; c0 < CIN_; c0 += 4, buf ^= 1) {
        // ---- weights via cp.async from pre-transposed g_wOmT
#pragma unroll
        for (int i = 0; i < 3; i++) {
            const int e = t + i * 128;
            if (e < 288) {
                const int c   = e / 72;
                const int rem = e % 72;
                const int tap = rem >> 3;
                const int oc4 = (rem & 7) * 4;
                cp16(&wA[buf][c][tap][oc4],
                     g_wOmT + ((c0 + c) * 9 + tap) * 32 + oc4);
            }
        }
        cp_commit();
        // ---- row cache (dup-stored): cols w0-1..w0+48 -> idx 0..49
#pragma unroll
        for (int i = 0; i < 5; i++) {
            const int e = t + i * 128;
            if (e < 600) {
                const int c  = e / 150;
                const int rr = e % 150;
                const int r  = rr / 50;
                const int cx = rr % 50;
                const int y   = h + r - 1;
                const int col = w0 + cx - 1;
                float v = 0.f;
                if ((unsigned)y < (unsigned)Hd && (unsigned)col < (unsigned)Wd)
                    v = __ldg(xb + (c0 + c) * HW_ + y * Wd + col);
                *reinterpret_cast<float2*>(&xr[buf][c][r][2 * cx]) = make_float2(v, v);
            }
        }
        cp_wait0();
        __syncthreads();

#pragma unroll
        for (int c = 0; c < 4; c++) {
#pragma unroll
            for (int ki = 0; ki < 3; ki++) {
                unsigned long long rd[5];
#pragma unroll
                for (int q = 0; q < 5; q++)
                    rd[q] = *reinterpret_cast<const unsigned long long*>(
                                &xr[buf][c][ki][2 * (px0 + q)]);
#pragma unroll
                for (int kj = 0; kj < 3; kj++) {
                    ulonglong2 wp = *reinterpret_cast<const ulonglong2*>(
                                        &wA[buf][c][ki * 3 + kj][oc0]);
#pragma unroll
                    for (int j = 0; j < 3; j++) {
                        fma2(acc[0][j], wp.x, rd[kj + j]);
                        fma2(acc[1][j], wp.y, rd[kj + j]);
                    }
                }
            }
        }
    }

    // ---- epilogue: g_om (27 ch) + offset output (18 ch)
    //      BOTH packed lanes must be bounds-guarded (oce can be 28/30).
#pragma unroll
    for (int i = 0; i < 2; i++)
#pragma unroll
        for (int j = 0; j < 3; j++) {
            float2 v = unpk(acc[i][j]);
            const int w = w0 + px0 + j;
            const int oce = oc0 + 2 * i;
            if (oce < 27)
                g_om[(b * 27 + oce) * HW_ + h * Wd + w] = v.x;
            if (oce + 1 < 27)
                g_om[(b * 27 + oce + 1) * HW_ + h * Wd + w] = v.y;
            if (oce < 18)
                outp[OUT_ELEMS + (b * 18 + oce) * HW_ + h * Wd + w] = v.x;
            if (oce + 1 < 18)
                outp[OUT_ELEMS + (b * 18 + oce + 1) * HW_ + h * Wd + w] = v.y;
        }
}

// ----------------------------------------------------------------------------
// Kernel 2: fused deformable im2col + GEMM, packed f32x2.
// Block tile: 128 oc x 48 px, 128 thr, micro 8 oc (4 pairs) x 6 px.
// Double-buffered KC=16 chunks, ONE sync per chunk: warps fill chunk i+1
// while others finish FMA of chunk i. As via cp.async from g_wT.
// Bs stored lane-duplicated -> packed B operands need no mov-dup.
// ----------------------------------------------------------------------------
__global__ __launch_bounds__(128) void dcn_main_kernel(
    const float* __restrict__ x,
    const float* __restrict__ bias,
    float* __restrict__ outp)
{
    __shared__ __align__(16) float As[2][KC][132];   // [kk][oc]
    __shared__ __align__(16) float Bs[2][KC][104];   // [kk][2*px] dup-stored
    __shared__ int4   sIdx[9 * 48];
    __shared__ float4 sWgt[9 * 48];
    __shared__ float  sBias[128];

    const int bx = blockIdx.x;
    const int wt = bx & 1;
    const int h  = (bx >> 1) % Hd;
    const int b  = bx / (2 * Hd);
    const int w0 = wt * 48;
    const int t  = threadIdx.x;
    const int ty = t >> 3;            // 0..15 -> oc0 = ty*8
    const int tx = t & 7;             // 0..7  -> px0 = tx*6
    const int oc0 = ty * 8;
    const int px0 = tx * 6;

    sBias[t] = bias[t];

    // ---- precompute bilinear sampling metadata per (tap, pixel)
    for (int e = t; e < 9 * 48; e += 128) {
        const int k = e / 48;
        const int p = e % 48;
        const int w = w0 + p;
        const float* om = g_om + (b * 27) * HW_ + h * Wd + w;
        const float o1 = om[k * HW_];
        const float o2 = om[(9 + k) * HW_];
        const float mr = om[(18 + k) * HW_];
        const float m  = __fdividef(2.f, 1.f + __expf(-mr));

        const int ki = k / 3, kj = k - ki * 3;
        const float py  = (float)(h - 1 + ki) + o1;
        const float pxf = (float)(w - 1 + kj) + o2;
        const float y0f = floorf(py), x0f = floorf(pxf);
        const float ly = py - y0f, lx = pxf - x0f;
        const int y0 = (int)y0f, x0 = (int)x0f;
        const int y1 = y0 + 1,  x1 = x0 + 1;

        const float v00 = ((unsigned)y0 < (unsigned)Hd && (unsigned)x0 < (unsigned)Wd) ? 1.f : 0.f;
        const float v01 = ((unsigned)y0 < (unsigned)Hd && (unsigned)x1 < (unsigned)Wd) ? 1.f : 0.f;
        const float v10 = ((unsigned)y1 < (unsigned)Hd && (unsigned)x0 < (unsigned)Wd) ? 1.f : 0.f;
        const float v11 = ((unsigned)y1 < (unsigned)Hd && (unsigned)x1 < (unsigned)Wd) ? 1.f : 0.f;

        const int y0c = min(max(y0, 0), Hd - 1), y1c = min(max(y1, 0), Hd - 1);
        const int x0c = min(max(x0, 0), Wd - 1), x1c = min(max(x1, 0), Wd - 1);

        sIdx[e] = make_int4(y0c * Wd + x0c, y0c * Wd + x1c,
                            y1c * Wd + x0c, y1c * Wd + x1c);
        const float hy = 1.f - ly, hx = 1.f - lx;
        sWgt[e] = make_float4(hy * hx * m * v00, hy * lx * m * v01,
                              ly * hx * m * v10, ly * lx * m * v11);
    }
    __syncthreads();

    unsigned long long acc[4][6];
#pragma unroll
    for (int i = 0; i < 4; i++)
#pragma unroll
        for (int j = 0; j < 6; j++) acc[i][j] = 0ull;

    const float* xb = x + b * CIN_ * HW_;
    int buf = 0;

    for (int kc = 0; kc < KKd; kc += KC, buf ^= 1) {
        // ---- As fill: 4x cp.async from pre-transposed weights
#pragma unroll
        for (int i = 0; i < 4; i++) {
            const int f   = t + i * 128;          // < 512
            const int kk  = f >> 5;
            const int oc4 = (f & 31) * 4;
            cp16(&As[buf][kk][oc4], g_wT + (kc + kk) * 128 + oc4);
        }
        cp_commit();
        // ---- Bs fill: deformable-sampled columns, dup-stored
#pragma unroll
        for (int i = 0; i < 6; i++) {
            const int e    = t + i * 128;         // < 768
            const int kk   = e / 48;
            const int p    = e % 48;
            const int kidx = kc + kk;
            const int c    = kidx / 9;
            const int k    = kidx - c * 9;
            const int4   id = sIdx[k * 48 + p];
            const float4 wv = sWgt[k * 48 + p];
            const float* xc = xb + c * HW_;
            const float v = wv.x * __ldg(xc + id.x)
                          + wv.y * __ldg(xc + id.y)
                          + wv.z * __ldg(xc + id.z)
                          + wv.w * __ldg(xc + id.w);
            *reinterpret_cast<float2*>(&Bs[buf][kk][2 * p]) = make_float2(v, v);
        }
        cp_wait0();
        __syncthreads();

        // ---- FMA over this chunk (other warps may already fill next buffer)
#pragma unroll
        for (int kk = 0; kk < KC; kk++) {
            ulonglong2 aA = *reinterpret_cast<const ulonglong2*>(&As[buf][kk][oc0]);
            ulonglong2 aB = *reinterpret_cast<const ulonglong2*>(&As[buf][kk][oc0 + 4]);
            const float* Brow = &Bs[buf][kk][2 * px0];
            ulonglong2 b01 = *reinterpret_cast<const ulonglong2*>(Brow);
            ulonglong2 b23 = *reinterpret_cast<const ulonglong2*>(Brow + 4);
            ulonglong2 b45 = *reinterpret_cast<const ulonglong2*>(Brow + 8);
            unsigned long long a[4] = {aA.x, aA.y, aB.x, aB.y};
            unsigned long long d[6] = {b01.x, b01.y, b23.x, b23.y, b45.x, b45.y};
#pragma unroll
            for (int i = 0; i < 4; i++)
#pragma unroll
                for (int j = 0; j < 6; j++)
                    fma2(acc[i][j], a[i], d[j]);
        }
    }

    // ---- epilogue: unpack oc-pairs, add bias, store
    const int w = w0 + px0;
#pragma unroll
    for (int i = 0; i < 4; i++) {
        const int oce = oc0 + 2 * i;
        const float be = sBias[oce];
        const float bo = sBias[oce + 1];
        float* pe = outp + (b * COUT_ + oce) * HW_ + h * Wd + w;
        float* po = pe + HW_;
#pragma unroll
        for (int j = 0; j < 6; j++) {
            float2 v = unpk(acc[i][j]);
            pe[j] = v.x + be;
            po[j] = v.y + bo;
        }
    }
}

// ----------------------------------------------------------------------------
extern "C" void kernel_launch(void* const* d_in, const int* in_sizes, int n_in,
                              void* d_out, int out_size)
{
    const float* x    = (const float*)d_in[0];   // [4,128,96,96]
    const float* wgt  = (const float*)d_in[1];   // [128,128,3,3]
    const float* bias = (const float*)d_in[2];   // [128]
    const float* wom  = (const float*)d_in[3];   // [27,128,3,3]
    float* outp = (float*)d_out;

    prep_kernel<<<720, 256>>>(wgt, wom);                   // transposes
    offconv_kernel<<<Bn * Hd * 2, 128>>>(x, outp);         // 768 blocks
    dcn_main_kernel<<<Bn * Hd * 2, 128>>>(x, bias, outp);  // 768 blocks
}

// round 10
// speedup vs baseline: 1.2567x; 1.0952x over previous
#include <cuda_runtime.h>
#include <math.h>

// ----------------------------------------------------------------------------
// ModulatedDeformableConv2d (DCNv2-style) with residual offset output.
//   B=4, CIN=COUT=128, K=3, S=1, P=1, D=1, H=W=96, MASK_SCALE=2
// d_out: out [4,128,96,96] then offset [4,18,96,96], float32.
// ----------------------------------------------------------------------------

namespace {
constexpr int Bn    = 4;
constexpr int CIN_  = 128;
constexpr int COUT_ = 128;
constexpr int Hd    = 96;
constexpr int Wd    = 96;
constexpr int HW_   = 9216;
constexpr int KKd   = CIN_ * 9;              // 1152
constexpr int OUT_ELEMS = Bn * COUT_ * HW_;  // 4718592
constexpr int KC    = 16;                    // k-chunk
}

__device__ float g_om[Bn * 27 * HW_];             // offset/mask conv scratch
__device__ __align__(16) float g_wT [KKd * 128];  // weight transposed [kk][oc]
__device__ __align__(16) float g_wOmT[KKd * 32];  // w_offmask transposed [kk][oc<32]

// ---- packed fp32x2 + cp.async helpers --------------------------------------
__device__ __forceinline__ void fma2(unsigned long long& d,
                                     unsigned long long a,
                                     unsigned long long b) {
    asm("fma.rn.f32x2 %0, %1, %2, %0;" : "+l"(d) : "l"(a), "l"(b));
}
__device__ __forceinline__ unsigned long long dup2(float v) {
    unsigned long long r;
    asm("mov.b64 %0, {%1, %1};" : "=l"(r) : "f"(v));
    return r;
}
__device__ __forceinline__ float2 unpk(unsigned long long v) {
    float2 r;
    asm("mov.b64 {%0, %1}, %2;" : "=f"(r.x), "=f"(r.y) : "l"(v));
    return r;
}
__device__ __forceinline__ void cp16(void* dst_smem, const void* src) {
    unsigned d = (unsigned)__cvta_generic_to_shared(dst_smem);
    asm volatile("cp.async.ca.shared.global [%0], [%1], 16;" :: "r"(d), "l"(src));
}
__device__ __forceinline__ void cp_commit() {
    asm volatile("cp.async.commit_group;");
}
__device__ __forceinline__ void cp_wait0() {
    asm volatile("cp.async.wait_group 0;" ::: "memory");
}

// ----------------------------------------------------------------------------
// Kernel 0: one-time (per launch) weight transposes.
// ----------------------------------------------------------------------------
__global__ __launch_bounds__(256) void prep_kernel(
    const float* __restrict__ weight, const float* __restrict__ wom)
{
    const int idx = blockIdx.x * 256 + threadIdx.x;     // 0..184319
    if (idx < KKd * 128) {
        const int kk = idx >> 7, oc = idx & 127;
        g_wT[idx] = __ldg(weight + oc * KKd + kk);
    } else {
        const int j = idx - KKd * 128;
        const int kk = j >> 5, oc = j & 31;
        g_wOmT[j] = (oc < 27) ? __ldg(wom + oc * KKd + kk) : 0.f;
    }
}

// ----------------------------------------------------------------------------
// Kernel 1: om = conv3x3(x, w_offmask), 27 ch, pad=1.  (unchanged from R7)
// ----------------------------------------------------------------------------
__global__ __launch_bounds__(128) void offconv_kernel(
    const float* __restrict__ x,
    float* __restrict__ outp)
{
    __shared__ __align__(16) float xr[2][4][3][104];  // dup-stored, cols 0..49
    __shared__ __align__(16) float wA[2][4][9][32];   // [c][tap][oc]

    const int bx = blockIdx.x;
    const int wt = bx & 1;
    const int h  = (bx >> 1) % Hd;
    const int b  = bx / (2 * Hd);
    const int w0 = wt * 48;
    const int t  = threadIdx.x;
    const int ty = t >> 4;            // 0..7  -> oc0 = ty*4
    const int tx = t & 15;            // 0..15 -> px0 = tx*3
    const int oc0 = ty * 4;
    const int px0 = tx * 3;

    unsigned long long acc[2][3];
#pragma unroll
    for (int i = 0; i < 2; i++)
#pragma unroll
        for (int j = 0; j < 3; j++) acc[i][j] = 0ull;

    const float* xb = x + b * CIN_ * HW_;
    int buf = 0;

    for (int c0 = 0; c0 < CIN_; c0 += 4, buf ^= 1) {
#pragma unroll
        for (int i = 0; i < 3; i++) {
            const int e = t + i * 128;
            if (e < 288) {
                const int c   = e / 72;
                const int rem = e % 72;
                const int tap = rem >> 3;
                const int oc4 = (rem & 7) * 4;
                cp16(&wA[buf][c][tap][oc4],
                     g_wOmT + ((c0 + c) * 9 + tap) * 32 + oc4);
            }
        }
        cp_commit();
#pragma unroll
        for (int i = 0; i < 5; i++) {
            const int e = t + i * 128;
            if (e < 600) {
                const int c  = e / 150;
                const int rr = e % 150;
                const int r  = rr / 50;
                const int cx = rr % 50;
                const int y   = h + r - 1;
                const int col = w0 + cx - 1;
                float v = 0.f;
                if ((unsigned)y < (unsigned)Hd && (unsigned)col < (unsigned)Wd)
                    v = __ldg(xb + (c0 + c) * HW_ + y * Wd + col);
                *reinterpret_cast<float2*>(&xr[buf][c][r][2 * cx]) = make_float2(v, v);
            }
        }
        cp_wait0();
        __syncthreads();

#pragma unroll
        for (int c = 0; c < 4; c++) {
#pragma unroll
            for (int ki = 0; ki < 3; ki++) {
                unsigned long long rd[5];
#pragma unroll
                for (int q = 0; q < 5; q++)
                    rd[q] = *reinterpret_cast<const unsigned long long*>(
                                &xr[buf][c][ki][2 * (px0 + q)]);
#pragma unroll
                for (int kj = 0; kj < 3; kj++) {
                    ulonglong2 wp = *reinterpret_cast<const ulonglong2*>(
                                        &wA[buf][c][ki * 3 + kj][oc0]);
#pragma unroll
                    for (int j = 0; j < 3; j++) {
                        fma2(acc[0][j], wp.x, rd[kj + j]);
                        fma2(acc[1][j], wp.y, rd[kj + j]);
                    }
                }
            }
        }
    }

    // ---- epilogue (both packed lanes bounds-guarded)
#pragma unroll
    for (int i = 0; i < 2; i++)
#pragma unroll
        for (int j = 0; j < 3; j++) {
            float2 v = unpk(acc[i][j]);
            const int w = w0 + px0 + j;
            const int oce = oc0 + 2 * i;
            if (oce < 27)
                g_om[(b * 27 + oce) * HW_ + h * Wd + w] = v.x;
            if (oce + 1 < 27)
                g_om[(b * 27 + oce + 1) * HW_ + h * Wd + w] = v.y;
            if (oce < 18)
                outp[OUT_ELEMS + (b * 18 + oce) * HW_ + h * Wd + w] = v.x;
            if (oce + 1 < 18)
                outp[OUT_ELEMS + (b * 18 + oce + 1) * HW_ + h * Wd + w] = v.y;
        }
}

// ----------------------------------------------------------------------------
// Kernel 2: fused deformable im2col + GEMM, packed f32x2.
// Block tile: 128 oc x 48 px, 128 thr, micro 8 oc (4 pairs) x 6 px.
// Single sync per double-buffered KC=16 chunk. R8: non-dup Bs (56B LDS/kk,
// register dup on ALU pipe), short4 indices, 3 blocks/SM.
// ----------------------------------------------------------------------------
__global__ __launch_bounds__(128, 3) void dcn_main_kernel(
    const float* __restrict__ x,
    const float* __restrict__ bias,
    float* __restrict__ outp)
{
    __shared__ __align__(16) float  As[2][KC][132];   // [kk][oc]
    __shared__ __align__(16) float  Bs[2][KC][52];    // [kk][px] non-dup
    __shared__ __align__(8)  ushort4 sIdx[9 * 48];    // corner indices (u16)
    __shared__ __align__(16) float4  sWgt[9 * 48];    // corner weights
    __shared__ float sBias[128];

    const int bx = blockIdx.x;
    const int wt = bx & 1;
    const int h  = (bx >> 1) % Hd;
    const int b  = bx / (2 * Hd);
    const int w0 = wt * 48;
    const int t  = threadIdx.x;
    const int ty = t >> 3;            // 0..15 -> oc0 = ty*8
    const int tx = t & 7;             // 0..7  -> px0 = tx*6
    const int oc0 = ty * 8;
    const int px0 = tx * 6;

    sBias[t] = bias[t];

    // ---- precompute bilinear sampling metadata per (tap, pixel)
    for (int e = t; e < 9 * 48; e += 128) {
        const int k = e / 48;
        const int p = e % 48;
        const int w = w0 + p;
        const float* om = g_om + (b * 27) * HW_ + h * Wd + w;
        const float o1 = om[k * HW_];
        const float o2 = om[(9 + k) * HW_];
        const float mr = om[(18 + k) * HW_];
        const float m  = __fdividef(2.f, 1.f + __expf(-mr));

        const int ki = k / 3, kj = k - ki * 3;
        const float py  = (float)(h - 1 + ki) + o1;
        const float pxf = (float)(w - 1 + kj) + o2;
        const float y0f = floorf(py), x0f = floorf(pxf);
        const float ly = py - y0f, lx = pxf - x0f;
        const int y0 = (int)y0f, x0 = (int)x0f;
        const int y1 = y0 + 1,  x1 = x0 + 1;

        const float v00 = ((unsigned)y0 < (unsigned)Hd && (unsigned)x0 < (unsigned)Wd) ? 1.f : 0.f;
        const float v01 = ((unsigned)y0 < (unsigned)Hd && (unsigned)x1 < (unsigned)Wd) ? 1.f : 0.f;
        const float v10 = ((unsigned)y1 < (unsigned)Hd && (unsigned)x0 < (unsigned)Wd) ? 1.f : 0.f;
        const float v11 = ((unsigned)y1 < (unsigned)Hd && (unsigned)x1 < (unsigned)Wd) ? 1.f : 0.f;

        const int y0c = min(max(y0, 0), Hd - 1), y1c = min(max(y1, 0), Hd - 1);
        const int x0c = min(max(x0, 0), Wd - 1), x1c = min(max(x1, 0), Wd - 1);

        sIdx[e] = make_ushort4((unsigned short)(y0c * Wd + x0c),
                               (unsigned short)(y0c * Wd + x1c),
                               (unsigned short)(y1c * Wd + x0c),
                               (unsigned short)(y1c * Wd + x1c));
        const float hy = 1.f - ly, hx = 1.f - lx;
        sWgt[e] = make_float4(hy * hx * m * v00, hy * lx * m * v01,
                              ly * hx * m * v10, ly * lx * m * v11);
    }
    __syncthreads();

    unsigned long long acc[4][6];
#pragma unroll
    for (int i = 0; i < 4; i++)
#pragma unroll
        for (int j = 0; j < 6; j++) acc[i][j] = 0ull;

    const float* xb = x + b * CIN_ * HW_;
    int buf = 0;

    for (int kc = 0; kc < KKd; kc += KC, buf ^= 1) {
        // ---- As fill: 4x cp.async from pre-transposed weights
#pragma unroll
        for (int i = 0; i < 4; i++) {
            const int f   = t + i * 128;          // < 512
            const int kk  = f >> 5;
            const int oc4 = (f & 31) * 4;
            cp16(&As[buf][kk][oc4], g_wT + (kc + kk) * 128 + oc4);
        }
        cp_commit();
        // ---- Bs fill: deformable-sampled columns
#pragma unroll
        for (int i = 0; i < 6; i++) {
            const int e    = t + i * 128;         // < 768
            const int kk   = e / 48;
            const int p    = e % 48;
            const int kidx = kc + kk;
            const int c    = kidx / 9;
            const int k    = kidx - c * 9;
            const ushort4 id = sIdx[k * 48 + p];
            const float4  wv = sWgt[k * 48 + p];
            const float* xc = xb + c * HW_;
            Bs[buf][kk][p] = wv.x * __ldg(xc + id.x)
                           + wv.y * __ldg(xc + id.y)
                           + wv.z * __ldg(xc + id.z)
                           + wv.w * __ldg(xc + id.w);
        }
        cp_wait0();
        __syncthreads();

        // ---- FMA over this chunk (fill of next chunk overlaps across warps)
#pragma unroll
        for (int kk = 0; kk < KC; kk++) {
            ulonglong2 aA = *reinterpret_cast<const ulonglong2*>(&As[buf][kk][oc0]);
            ulonglong2 aB = *reinterpret_cast<const ulonglong2*>(&As[buf][kk][oc0 + 4]);
            float2 b0 = *reinterpret_cast<const float2*>(&Bs[buf][kk][px0]);
            float2 b1 = *reinterpret_cast<const float2*>(&Bs[buf][kk][px0 + 2]);
            float2 b2 = *reinterpret_cast<const float2*>(&Bs[buf][kk][px0 + 4]);
            unsigned long long a[4] = {aA.x, aA.y, aB.x, aB.y};
            unsigned long long d[6] = {dup2(b0.x), dup2(b0.y), dup2(b1.x),
                                       dup2(b1.y), dup2(b2.x), dup2(b2.y)};
#pragma unroll
            for (int i = 0; i < 4; i++)
#pragma unroll
                for (int j = 0; j < 6; j++)
                    fma2(acc[i][j], a[i], d[j]);
        }
    }

    // ---- epilogue: unpack oc-pairs, add bias, store
    const int w = w0 + px0;
#pragma unroll
    for (int i = 0; i < 4; i++) {
        const int oce = oc0 + 2 * i;
        const float be = sBias[oce];
        const float bo = sBias[oce + 1];
        float* pe = outp + (b * COUT_ + oce) * HW_ + h * Wd + w;
        float* po = pe + HW_;
#pragma unroll
        for (int j = 0; j < 6; j++) {
            float2 v = unpk(acc[i][j]);
            pe[j] = v.x + be;
            po[j] = v.y + bo;
        }
    }
}

// ----------------------------------------------------------------------------
extern "C" void kernel_launch(void* const* d_in, const int* in_sizes, int n_in,
                              void* d_out, int out_size)
{
    const float* x    = (const float*)d_in[0];   // [4,128,96,96]
    const float* wgt  = (const float*)d_in[1];   // [128,128,3,3]
    const float* bias = (const float*)d_in[2];   // [128]
    const float* wom  = (const float*)d_in[3];   // [27,128,3,3]
    float* outp = (float*)d_out;

    prep_kernel<<<720, 256>>>(wgt, wom);                   // transposes
    offconv_kernel<<<Bn * Hd * 2, 128>>>(x, outp);         // 768 blocks
    dcn_main_kernel<<<Bn * Hd * 2, 128>>>(x, bias, outp);  // 768 blocks
}